// round 2
// baseline (speedup 1.0000x reference)
#include <cuda_runtime.h>
#include <cuda_bf16.h>

#define N_NODES 50000
#define N_EDGES 600000
#define IN_CH 128
#define HID_CH 128
#define OUT_CH 64
#define NUM_GRAPHS 512

// ---------------- device scratch (no allocations allowed) ----------------
__device__ float g_t1[N_NODES * HID_CH];       // 25.6 MB
__device__ float g_t2[N_NODES * HID_CH];       // 25.6 MB
__device__ int   g_cnt[N_NODES];
__device__ float g_dinv[N_NODES];
__device__ int   g_rowptr[N_NODES + 1];
__device__ int   g_cursor[N_NODES];
__device__ int   g_csrsrc[N_EDGES];
__device__ float g_pool[NUM_GRAPHS * HID_CH];
__device__ float g_pcnt[NUM_GRAPHS];

// ---------------- init: zero counters & pool buffers ----------------
__global__ void init_kernel() {
    int i = blockIdx.x * blockDim.x + threadIdx.x;   // 65536 threads
    if (i < N_NODES) g_cnt[i] = 0;
    if (i < NUM_GRAPHS * HID_CH) g_pool[i] = 0.0f;
    if (i < NUM_GRAPHS) g_pcnt[i] = 0.0f;
}

// ---------------- histogram of in-degrees (real edges only) ----------------
__global__ void hist_kernel(const int* __restrict__ dst) {
    int i = blockIdx.x * blockDim.x + threadIdx.x;
    if (i < N_EDGES) atomicAdd(&g_cnt[dst[i]], 1);
}

// ---------------- single-block exclusive scan -> rowptr, cursor, dinv ----------------
__global__ void scan_kernel() {
    __shared__ int part[1024];
    const int tid = threadIdx.x;
    const int chunk = (N_NODES + 1023) / 1024;   // 49
    int start = tid * chunk;
    int end = start + chunk; if (end > N_NODES) end = N_NODES;
    int s = 0;
    for (int i = start; i < end; i++) s += g_cnt[i];
    part[tid] = s;
    __syncthreads();
    // Hillis-Steele inclusive scan
    for (int off = 1; off < 1024; off <<= 1) {
        int v = 0;
        if (tid >= off) v = part[tid - off];
        __syncthreads();
        part[tid] += v;
        __syncthreads();
    }
    int run = (tid == 0) ? 0 : part[tid - 1];
    for (int i = start; i < end; i++) {
        g_rowptr[i] = run;
        g_cursor[i] = run;
        g_dinv[i] = rsqrtf((float)(g_cnt[i] + 1));  // +1 self-loop
        run += g_cnt[i];
    }
    if (tid == 1023) g_rowptr[N_NODES] = part[1023];
}

// ---------------- fill CSR (src indices grouped by dst) ----------------
__global__ void fill_kernel(const int* __restrict__ src,
                            const int* __restrict__ dst) {
    int i = blockIdx.x * blockDim.x + threadIdx.x;
    if (i < N_EDGES) {
        int d = dst[i];
        int pos = atomicAdd(&g_cursor[d], 1);
        g_csrsrc[pos] = src[i];
    }
}

// ---------------- GEMM: C[M,128] = A[M,128] @ W[128,128] ----------------
// 128x128 output tile / block, 256 threads, 8x8 micro-tile per thread.
#define XS_STRIDE 132
__global__ __launch_bounds__(256) void gemm128(const float* __restrict__ A,
                                               const float* __restrict__ W,
                                               float* __restrict__ C, int M) {
    extern __shared__ float sm[];
    float* wsf = sm;                 // 128*128 = 16384 floats, W[k][n]
    float* xsf = sm + 16384;         // 32*132  = 4224 floats, x^T chunk [k][r]
    const int tid = threadIdx.x;

    // load full W once
    for (int i = tid; i < 4096; i += 256)
        ((float4*)wsf)[i] = ((const float4*)W)[i];

    const int row0 = blockIdx.x * 128;
    const int tx = tid & 15, ty = tid >> 4;
    const int r0 = ty * 8, c0 = tx * 8;

    float acc[8][8];
#pragma unroll
    for (int i = 0; i < 8; i++)
#pragma unroll
        for (int j = 0; j < 8; j++) acc[i][j] = 0.0f;

    for (int kc = 0; kc < 128; kc += 32) {
        __syncthreads();
        // load 128 rows x 32 k, transposed into xs[k][r]
        for (int i = tid; i < 1024; i += 256) {
            int r = i >> 3, k4 = i & 7;
            int row = row0 + r;
            float4 v = make_float4(0.f, 0.f, 0.f, 0.f);
            if (row < M) v = *(const float4*)&A[row * 128 + kc + k4 * 4];
            int kb = k4 * 4;
            xsf[(kb + 0) * XS_STRIDE + r] = v.x;
            xsf[(kb + 1) * XS_STRIDE + r] = v.y;
            xsf[(kb + 2) * XS_STRIDE + r] = v.z;
            xsf[(kb + 3) * XS_STRIDE + r] = v.w;
        }
        __syncthreads();
#pragma unroll
        for (int kk = 0; kk < 32; kk++) {
            float4 a0 = *(float4*)&xsf[kk * XS_STRIDE + r0];
            float4 a1 = *(float4*)&xsf[kk * XS_STRIDE + r0 + 4];
            float4 b0 = *(float4*)&wsf[(kc + kk) * 128 + c0];
            float4 b1 = *(float4*)&wsf[(kc + kk) * 128 + c0 + 4];
            float a[8] = {a0.x, a0.y, a0.z, a0.w, a1.x, a1.y, a1.z, a1.w};
            float b[8] = {b0.x, b0.y, b0.z, b0.w, b1.x, b1.y, b1.z, b1.w};
#pragma unroll
            for (int i = 0; i < 8; i++)
#pragma unroll
                for (int j = 0; j < 8; j++) acc[i][j] += a[i] * b[j];
        }
    }

#pragma unroll
    for (int i = 0; i < 8; i++) {
        int row = row0 + r0 + i;
        if (row < M) {
            *(float4*)&C[row * 128 + c0]     = make_float4(acc[i][0], acc[i][1], acc[i][2], acc[i][3]);
            *(float4*)&C[row * 128 + c0 + 4] = make_float4(acc[i][4], acc[i][5], acc[i][6], acc[i][7]);
        }
    }
}
#define GEMM_SMEM ((16384 + 32 * XS_STRIDE) * 4)

// ---------------- aggregation: out[d] = relu(sum_e h[s]*dinv[s]*dinv[d] + h[d]*dinv[d]^2 + b) ----------------
__global__ void agg_kernel(const float* __restrict__ hin,
                           float* __restrict__ hout,
                           const float* __restrict__ bias) {
    int gid = blockIdx.x * blockDim.x + threadIdx.x;
    int node = gid >> 5;
    int lane = gid & 31;
    if (node >= N_NODES) return;

    const float dv = g_dinv[node];
    const float4* h4 = (const float4*)hin;

    float4 acc = __ldg(&h4[node * 32 + lane]);
    float sl = dv * dv;                       // self-loop coef
    acc.x *= sl; acc.y *= sl; acc.z *= sl; acc.w *= sl;

    int e0 = g_rowptr[node];
    int e1 = g_rowptr[node + 1];
    for (int e = e0; e < e1; e++) {
        int s = g_csrsrc[e];
        float c = g_dinv[s] * dv;
        float4 v = __ldg(&h4[s * 32 + lane]);
        acc.x += v.x * c; acc.y += v.y * c; acc.z += v.z * c; acc.w += v.w * c;
    }

    float4 b = ((const float4*)bias)[lane];
    acc.x = fmaxf(acc.x + b.x, 0.0f);
    acc.y = fmaxf(acc.y + b.y, 0.0f);
    acc.z = fmaxf(acc.z + b.z, 0.0f);
    acc.w = fmaxf(acc.w + b.w, 0.0f);
    ((float4*)hout)[node * 32 + lane] = acc;
}

// ---------------- pooling: atomic segment-sum over graphs ----------------
__global__ void pool_kernel(const float* __restrict__ h,
                            const int* __restrict__ batch) {
    int gid = blockIdx.x * blockDim.x + threadIdx.x;
    int node = gid >> 5;
    int lane = gid & 31;
    if (node >= N_NODES) return;
    int g = batch[node];
    float4 v = ((const float4*)h)[node * 32 + lane];
    atomicAdd(&g_pool[g * 128 + lane * 4 + 0], v.x);
    atomicAdd(&g_pool[g * 128 + lane * 4 + 1], v.y);
    atomicAdd(&g_pool[g * 128 + lane * 4 + 2], v.z);
    atomicAdd(&g_pool[g * 128 + lane * 4 + 3], v.w);
    if (lane == 0) atomicAdd(&g_pcnt[g], 1.0f);
}

// ---------------- final: out[512,64] = (pool/cnt) @ Wlin + blin ----------------
__global__ void final_kernel(const float* __restrict__ Wlin,
                             const float* __restrict__ blin,
                             float* __restrict__ out) {
    __shared__ float ws[HID_CH * OUT_CH];
    __shared__ float bs[OUT_CH];
    for (int i = threadIdx.x; i < HID_CH * OUT_CH; i += 256) ws[i] = Wlin[i];
    if (threadIdx.x < OUT_CH) bs[threadIdx.x] = blin[threadIdx.x];
    __syncthreads();

    int t = blockIdx.x * 256 + threadIdx.x;    // 0..32767
    int g = t >> 6, o = t & 63;
    float inv = 1.0f / fmaxf(g_pcnt[g], 1.0f);
    float s = 0.0f;
#pragma unroll 8
    for (int k = 0; k < 128; k++)
        s += g_pool[g * 128 + k] * ws[k * 64 + o];
    out[t] = s * inv + bs[o];
}

// ---------------- launch ----------------
extern "C" void kernel_launch(void* const* d_in, const int* in_sizes, int n_in,
                              void* d_out, int out_size) {
    const float* x    = (const float*)d_in[0];
    const float* W1   = (const float*)d_in[1];
    const float* b1   = (const float*)d_in[2];
    const float* W2   = (const float*)d_in[3];
    const float* b2   = (const float*)d_in[4];
    const float* Wlin = (const float*)d_in[5];
    const float* blin = (const float*)d_in[6];
    const int* edge   = (const int*)d_in[7];     // JAX default: int64 -> int32
    const int* batch  = (const int*)d_in[8];
    float* out = (float*)d_out;

    const int* src = edge;
    const int* dst = edge + N_EDGES;

    float *t1, *t2;
    cudaGetSymbolAddress((void**)&t1, g_t1);
    cudaGetSymbolAddress((void**)&t2, g_t2);

    cudaFuncSetAttribute(gemm128, cudaFuncAttributeMaxDynamicSharedMemorySize, GEMM_SMEM);

    const int eb = (N_EDGES + 255) / 256;               // 2344
    const int gb = (N_NODES + 127) / 128;               // 391
    const int ab = (N_NODES * 32) / 256;                // 6250

    init_kernel<<<256, 256>>>();
    hist_kernel<<<eb, 256>>>(dst);
    scan_kernel<<<1, 1024>>>();
    fill_kernel<<<eb, 256>>>(src, dst);

    gemm128<<<gb, 256, GEMM_SMEM>>>(x, W1, t1, N_NODES);
    agg_kernel<<<ab, 256>>>(t1, t2, b1);

    gemm128<<<gb, 256, GEMM_SMEM>>>(t2, W2, t1, N_NODES);
    agg_kernel<<<ab, 256>>>(t1, t2, b2);

    pool_kernel<<<ab, 256>>>(t2, batch);
    final_kernel<<<128, 256>>>(Wlin, blin, out);
}